// round 1
// baseline (speedup 1.0000x reference)
#include <cuda_runtime.h>
#include <math.h>

#define B_    64
#define P_    196
#define ENC_  512
#define EMB_  256
#define ATT_  256
#define DEC_  256
#define V_    10000
#define T_    44
#define NG_   1024           // 4*DEC
#define KX_   1024           // ENC + EMB + DEC
#define SPLITK_ 16           // gates GEMM K chunks of 64

// ---------------- device scratch (static: no allocation allowed) ----------------
__device__ float g_att1[B_ * P_ * ATT_];      // 12.8 MB  encoder attention keys
__device__ float g_WdaT[ATT_ * DEC_];         // W_dec_att transposed [k][j]
__device__ float g_Wcat[NG_ * KX_];           // [W_ih | W_hh] combined, row-major [j][k]
__device__ float g_h0[B_ * DEC_];
__device__ float g_c[B_ * DEC_];
__device__ float g_x[B_ * KX_];               // per-step LSTM input [ctx | emb | h]
__device__ float g_gpart[SPLITK_ * B_ * NG_]; // split-K gate partials
__device__ float g_hall[T_ * B_ * DEC_];      // all hidden states for batched logits

__device__ __forceinline__ float sigm(float x) { return 1.0f / (1.0f + expf(-x)); }

// ---------------- one-time weight prep (transpose / concat) ----------------
__global__ void k_prep(const float* __restrict__ W_ih, const float* __restrict__ W_hh,
                       const float* __restrict__ W_dec_att) {
    int idx = blockIdx.x * blockDim.x + threadIdx.x;
    if (idx < NG_ * KX_) {
        int j = idx >> 10, k = idx & 1023;
        g_Wcat[idx] = (k < 768) ? W_ih[j * 768 + k] : W_hh[j * 256 + (k - 768)];
    }
    int idx2 = idx - NG_ * KX_;
    if (idx2 >= 0 && idx2 < ATT_ * DEC_) {
        int k = idx2 >> 8, j = idx2 & 255;
        g_WdaT[idx2] = W_dec_att[j * 256 + k];
    }
}

// ---------------- init h0/c0 from mean-pooled encoder ----------------
__global__ void k_init(const float* __restrict__ enc,
                       const float* __restrict__ W_init_h, const float* __restrict__ b_init_h,
                       const float* __restrict__ W_init_c, const float* __restrict__ b_init_c) {
    int b = blockIdx.x, tid = threadIdx.x;
    __shared__ float avg[ENC_];
    #pragma unroll
    for (int e0 = 0; e0 < 2; e0++) {
        int e = tid + e0 * 256;
        float s = 0.f;
        for (int p = 0; p < P_; p++) s += enc[((size_t)(b * P_ + p)) * ENC_ + e];
        avg[e] = s * (1.0f / (float)P_);
    }
    __syncthreads();
    float h = b_init_h[tid], c = b_init_c[tid];
    const float* wh = W_init_h + (size_t)tid * ENC_;
    const float* wc = W_init_c + (size_t)tid * ENC_;
    #pragma unroll 8
    for (int k = 0; k < ENC_; k++) { h += avg[k] * wh[k]; c += avg[k] * wc[k]; }
    g_h0[b * DEC_ + tid] = h;
    g_c[b * DEC_ + tid] = c;
}

// ---------------- generic 64x64 tiled SGEMM: C[m][n] = sum_k A[m][k]*Bm[n][k] (+bias) ----
// PERM=1: row m encodes (t*B + b); store to C[(b*T + t)*V + n] (logits epilogue)
template<int PERM>
__global__ void sgemm64(const float* __restrict__ A, const float* __restrict__ Bm,
                        const float* __restrict__ bias, float* __restrict__ C,
                        int M, int N, int K) {
    __shared__ float As[32][68];
    __shared__ float Bs[32][68];
    int tid = threadIdx.x;
    int m0 = blockIdx.x * 64, n0 = blockIdx.y * 64;
    int tx = tid & 15, ty = tid >> 4;
    float acc[4][4] = {};
    for (int k0 = 0; k0 < K; k0 += 32) {
        #pragma unroll
        for (int r = 0; r < 8; r++) {
            int row = r * 8 + (tid >> 5);
            int k = tid & 31;
            As[k][row] = A[(size_t)(m0 + row) * K + k0 + k];
            Bs[k][row] = (n0 + row < N) ? Bm[(size_t)(n0 + row) * K + k0 + k] : 0.f;
        }
        __syncthreads();
        #pragma unroll
        for (int kk = 0; kk < 32; kk++) {
            float4 a4 = *(const float4*)&As[kk][ty * 4];
            float4 b4 = *(const float4*)&Bs[kk][tx * 4];
            acc[0][0] += a4.x * b4.x; acc[0][1] += a4.x * b4.y; acc[0][2] += a4.x * b4.z; acc[0][3] += a4.x * b4.w;
            acc[1][0] += a4.y * b4.x; acc[1][1] += a4.y * b4.y; acc[1][2] += a4.y * b4.z; acc[1][3] += a4.y * b4.w;
            acc[2][0] += a4.z * b4.x; acc[2][1] += a4.z * b4.y; acc[2][2] += a4.z * b4.z; acc[2][3] += a4.z * b4.w;
            acc[3][0] += a4.w * b4.x; acc[3][1] += a4.w * b4.y; acc[3][2] += a4.w * b4.z; acc[3][3] += a4.w * b4.w;
        }
        __syncthreads();
    }
    #pragma unroll
    for (int i = 0; i < 4; i++) {
        int m = m0 + ty * 4 + i;
        #pragma unroll
        for (int j = 0; j < 4; j++) {
            int n = n0 + tx * 4 + j;
            if (n < N) {
                float v = acc[i][j] + (bias ? bias[n] : 0.f);
                if (PERM) {
                    int b = m & (B_ - 1), t = m >> 6;
                    C[((size_t)b * T_ + t) * V_ + n] = v;
                } else {
                    C[(size_t)m * N + n] = v;
                }
            }
        }
    }
}

// ---------------- per-step: finish previous cell, attention, softmax, ctx, build x ------
__device__ __forceinline__ void cell_update(int t, int b, int tid,
                                            const float* __restrict__ b_ih,
                                            const float* __restrict__ b_hh,
                                            float* h_out) {
    int j = tid;
    float gi = b_ih[j]       + b_hh[j];
    float gf = b_ih[j + 256] + b_hh[j + 256];
    float gg = b_ih[j + 512] + b_hh[j + 512];
    float go = b_ih[j + 768] + b_hh[j + 768];
    #pragma unroll
    for (int s = 0; s < SPLITK_; s++) {
        const float* gp = g_gpart + ((size_t)s * B_ + b) * NG_;
        gi += gp[j]; gf += gp[j + 256]; gg += gp[j + 512]; go += gp[j + 768];
    }
    float c  = g_c[b * DEC_ + tid];
    float cn = sigm(gf) * c + sigm(gi) * tanhf(gg);
    float hn = sigm(go) * tanhf(cn);
    g_c[b * DEC_ + tid] = cn;
    g_hall[((size_t)(t - 1) * B_ + b) * DEC_ + tid] = hn;
    if (h_out) h_out[tid] = hn;
}

__global__ void k_step(int t, const float* __restrict__ enc, const float* __restrict__ Wfull,
                       const float* __restrict__ embedding, const int* __restrict__ caption,
                       const float* __restrict__ b_ih, const float* __restrict__ b_hh,
                       float* __restrict__ alphas_out) {
    int b = blockIdx.x, tid = threadIdx.x;
    __shared__ float h_sh[256], att2[256], wf[256], sc[256], red[256];

    if (t > 0) cell_update(t, b, tid, b_ih, b_hh, h_sh);
    else       h_sh[tid] = g_h0[b * DEC_ + tid];
    wf[tid] = Wfull[tid];
    __syncthreads();

    // att2[j] = h . W_dec_att[j,:]  (WdaT is k-major -> coalesced)
    float a2 = 0.f;
    #pragma unroll 8
    for (int k = 0; k < 256; k++) a2 += h_sh[k] * g_WdaT[k * 256 + tid];
    att2[tid] = a2;
    __syncthreads();

    // scores: warp per p
    int lane = tid & 31, wid = tid >> 5;
    for (int p = wid; p < P_; p += 8) {
        const float* row = g_att1 + ((size_t)(b * P_ + p)) * ATT_;
        float s = 0.f;
        #pragma unroll
        for (int a = lane; a < 256; a += 32) {
            float v = row[a] + att2[a];
            s += fmaxf(v, 0.f) * wf[a];
        }
        #pragma unroll
        for (int o = 16; o > 0; o >>= 1) s += __shfl_down_sync(0xffffffffu, s, o);
        if (lane == 0) sc[p] = s;
    }
    __syncthreads();

    // softmax over P=196
    red[tid] = (tid < P_) ? sc[tid] : -1e30f;
    __syncthreads();
    for (int s = 128; s > 0; s >>= 1) { if (tid < s) red[tid] = fmaxf(red[tid], red[tid + s]); __syncthreads(); }
    float mx = red[0];
    __syncthreads();
    float ex = (tid < P_) ? expf(sc[tid] - mx) : 0.f;
    red[tid] = ex;
    __syncthreads();
    for (int s = 128; s > 0; s >>= 1) { if (tid < s) red[tid] += red[tid + s]; __syncthreads(); }
    float inv = 1.0f / red[0];
    __syncthreads();
    float alpha = ex * inv;
    if (tid < P_) {
        sc[tid] = alpha;
        alphas_out[((size_t)b * T_ + t) * P_ + tid] = alpha;
    }
    __syncthreads();

    // ctx[e] = sum_p alpha[p] * enc[b,p,e]  (coalesced over e)
    #pragma unroll
    for (int e0 = 0; e0 < 2; e0++) {
        int e = tid + e0 * 256;
        float s = 0.f;
        for (int p = 0; p < P_; p++) s += sc[p] * enc[((size_t)(b * P_ + p)) * ENC_ + e];
        g_x[b * KX_ + e] = s;
    }
    // x = [ctx | emb_t | h]
    int tok = caption[b * T_ + t];
    g_x[b * KX_ + ENC_ + tid]        = embedding[(size_t)tok * EMB_ + tid];
    g_x[b * KX_ + ENC_ + EMB_ + tid] = h_sh[tid];
}

__global__ void k_cell_final(const float* __restrict__ b_ih, const float* __restrict__ b_hh) {
    cell_update(T_, blockIdx.x, threadIdx.x, b_ih, b_hh, nullptr);
}

// ---------------- gates GEMM, split-K: gpart[sk][b][j] = sum_{k in chunk} x[b][k]*Wcat[j][k]
__global__ void k_gates() {
    __shared__ float Xs[64][68];
    __shared__ float Ws[64][68];
    int tid = threadIdx.x;
    int j0 = blockIdx.x * 64;
    int k0 = blockIdx.y * 64;
    #pragma unroll
    for (int r = 0; r < 16; r++) {
        int row = r * 4 + (tid >> 6);
        int k = tid & 63;
        Xs[k][row] = g_x[(size_t)row * KX_ + k0 + k];
        Ws[k][row] = g_Wcat[(size_t)(j0 + row) * KX_ + k0 + k];
    }
    __syncthreads();
    int tx = tid & 15, ty = tid >> 4;
    float acc[4][4] = {};
    #pragma unroll
    for (int kk = 0; kk < 64; kk++) {
        float4 xb = *(const float4*)&Xs[kk][ty * 4];
        float4 wj = *(const float4*)&Ws[kk][tx * 4];
        acc[0][0] += xb.x * wj.x; acc[0][1] += xb.x * wj.y; acc[0][2] += xb.x * wj.z; acc[0][3] += xb.x * wj.w;
        acc[1][0] += xb.y * wj.x; acc[1][1] += xb.y * wj.y; acc[1][2] += xb.y * wj.z; acc[1][3] += xb.y * wj.w;
        acc[2][0] += xb.z * wj.x; acc[2][1] += xb.z * wj.y; acc[2][2] += xb.z * wj.z; acc[2][3] += xb.z * wj.w;
        acc[3][0] += xb.w * wj.x; acc[3][1] += xb.w * wj.y; acc[3][2] += xb.w * wj.z; acc[3][3] += xb.w * wj.w;
    }
    #pragma unroll
    for (int bi = 0; bi < 4; bi++) {
        int b = ty * 4 + bi;
        #pragma unroll
        for (int ji = 0; ji < 4; ji++) {
            g_gpart[((size_t)blockIdx.y * B_ + b) * NG_ + j0 + tx * 4 + ji] = acc[bi][ji];
        }
    }
}

// ---------------- launch ----------------
extern "C" void kernel_launch(void* const* d_in, const int* in_sizes, int n_in,
                              void* d_out, int out_size) {
    const float* enc       = (const float*)d_in[0];
    const int*   caption   = (const int*)  d_in[1];
    const float* W_enc_att = (const float*)d_in[2];
    const float* W_dec_att = (const float*)d_in[3];
    const float* W_full    = (const float*)d_in[4];
    const float* embedding = (const float*)d_in[5];
    const float* W_init_h  = (const float*)d_in[6];
    const float* b_init_h  = (const float*)d_in[7];
    const float* W_init_c  = (const float*)d_in[8];
    const float* b_init_c  = (const float*)d_in[9];
    const float* W_ih      = (const float*)d_in[10];
    const float* b_ih      = (const float*)d_in[11];
    const float* W_hh      = (const float*)d_in[12];
    const float* b_hh      = (const float*)d_in[13];
    const float* W_out     = (const float*)d_in[14];
    const float* b_out     = (const float*)d_in[15];

    float* out    = (float*)d_out;
    float* preds  = out;                              // [B, T, V]
    float* alphas = out + (size_t)B_ * T_ * V_;       // [B, T, P]

    float *att1p, *hallp;
    cudaGetSymbolAddress((void**)&att1p, g_att1);
    cudaGetSymbolAddress((void**)&hallp, g_hall);

    // one-time prep
    k_prep<<<(NG_ * KX_ + ATT_ * DEC_ + 255) / 256, 256>>>(W_ih, W_hh, W_dec_att);
    k_init<<<B_, 256>>>(enc, W_init_h, b_init_h, W_init_c, b_init_c);
    // att1[b,p,a] = enc[b,p,:] . W_enc_att[a,:]   (M=12544, N=256, K=512)
    sgemm64<0><<<dim3(196, 4), 256>>>(enc, W_enc_att, nullptr, att1p, B_ * P_, ATT_, ENC_);

    // recurrence: 2 kernels per step
    for (int t = 0; t < T_; t++) {
        k_step<<<B_, 256>>>(t, enc, W_full, embedding, caption, b_ih, b_hh, alphas);
        k_gates<<<dim3(NG_ / 64, SPLITK_), 256>>>();
    }
    k_cell_final<<<B_, 256>>>(b_ih, b_hh);

    // batched logits: [T*B, DEC] @ W_out^T, permuted store into [B, T, V]
    sgemm64<1><<<dim3((T_ * B_) / 64, (V_ + 63) / 64), 256>>>(hallp, W_out, b_out, preds,
                                                              T_ * B_, V_, DEC_);
}

// round 2
// speedup vs baseline: 1.0057x; 1.0057x over previous
#include <cuda_runtime.h>
#include <math.h>

#define B_    64
#define P_    196
#define ENC_  512
#define EMB_  256
#define ATT_  256
#define DEC_  256
#define V_    10000
#define T_    44
#define NG_   1024           // 4*DEC
#define KX_   1024           // ENC + EMB + DEC
#define SPLITK_ 16           // gates GEMM K chunks of 64

// ---------------- device scratch (static: no allocation allowed) ----------------
__device__ float g_att1[B_ * P_ * ATT_];      // 12.8 MB  encoder attention keys
__device__ float g_WdaT[ATT_ * DEC_];         // W_dec_att transposed [k][j]
__device__ float g_Wcat[NG_ * KX_];           // [W_ih | W_hh] combined, row-major [j][k]
__device__ float g_h0[B_ * DEC_];
__device__ float g_c[B_ * DEC_];
__device__ float g_x[B_ * KX_];               // per-step LSTM input [ctx | emb | h]
__device__ float g_gpart[SPLITK_ * B_ * NG_]; // split-K gate partials
__device__ float g_hall[T_ * B_ * DEC_];      // all hidden states for batched logits

__device__ __forceinline__ float sigm(float x) { return 1.0f / (1.0f + expf(-x)); }

// ---------------- one-time weight prep (transpose / concat) ----------------
__global__ void k_prep(const float* __restrict__ W_ih, const float* __restrict__ W_hh,
                       const float* __restrict__ W_dec_att) {
    int idx = blockIdx.x * blockDim.x + threadIdx.x;
    if (idx < NG_ * KX_) {
        int j = idx >> 10, k = idx & 1023;
        g_Wcat[idx] = (k < 768) ? W_ih[j * 768 + k] : W_hh[j * 256 + (k - 768)];
    }
    int idx2 = idx - NG_ * KX_;
    if (idx2 >= 0 && idx2 < ATT_ * DEC_) {
        int k = idx2 >> 8, j = idx2 & 255;
        g_WdaT[idx2] = W_dec_att[j * 256 + k];
    }
}

// ---------------- init h0/c0 from mean-pooled encoder ----------------
__global__ void k_init(const float* __restrict__ enc,
                       const float* __restrict__ W_init_h, const float* __restrict__ b_init_h,
                       const float* __restrict__ W_init_c, const float* __restrict__ b_init_c) {
    int b = blockIdx.x, tid = threadIdx.x;
    __shared__ float avg[ENC_];
    #pragma unroll
    for (int e0 = 0; e0 < 2; e0++) {
        int e = tid + e0 * 256;
        float s = 0.f;
        for (int p = 0; p < P_; p++) s += enc[((size_t)(b * P_ + p)) * ENC_ + e];
        avg[e] = s * (1.0f / (float)P_);
    }
    __syncthreads();
    float h = b_init_h[tid], c = b_init_c[tid];
    const float* wh = W_init_h + (size_t)tid * ENC_;
    const float* wc = W_init_c + (size_t)tid * ENC_;
    #pragma unroll 8
    for (int k = 0; k < ENC_; k++) { h += avg[k] * wh[k]; c += avg[k] * wc[k]; }
    g_h0[b * DEC_ + tid] = h;
    g_c[b * DEC_ + tid] = c;
}

// ---------------- generic 64x64 tiled SGEMM: C[m][n] = sum_k A[m][k]*Bm[n][k] (+bias) ----
// PERM=1: row m encodes (t*B + b); store to C[(b*T + t)*V + n] (logits epilogue)
template<int PERM>
__global__ void sgemm64(const float* __restrict__ A, const float* __restrict__ Bm,
                        const float* __restrict__ bias, float* __restrict__ C,
                        int M, int N, int K) {
    __shared__ float As[32][68];
    __shared__ float Bs[32][68];
    int tid = threadIdx.x;
    int m0 = blockIdx.x * 64, n0 = blockIdx.y * 64;
    int tx = tid & 15, ty = tid >> 4;
    float acc[4][4] = {};
    for (int k0 = 0; k0 < K; k0 += 32) {
        #pragma unroll
        for (int r = 0; r < 8; r++) {
            int row = r * 8 + (tid >> 5);
            int k = tid & 31;
            As[k][row] = A[(size_t)(m0 + row) * K + k0 + k];
            Bs[k][row] = (n0 + row < N) ? Bm[(size_t)(n0 + row) * K + k0 + k] : 0.f;
        }
        __syncthreads();
        #pragma unroll
        for (int kk = 0; kk < 32; kk++) {
            float4 a4 = *(const float4*)&As[kk][ty * 4];
            float4 b4 = *(const float4*)&Bs[kk][tx * 4];
            acc[0][0] += a4.x * b4.x; acc[0][1] += a4.x * b4.y; acc[0][2] += a4.x * b4.z; acc[0][3] += a4.x * b4.w;
            acc[1][0] += a4.y * b4.x; acc[1][1] += a4.y * b4.y; acc[1][2] += a4.y * b4.z; acc[1][3] += a4.y * b4.w;
            acc[2][0] += a4.z * b4.x; acc[2][1] += a4.z * b4.y; acc[2][2] += a4.z * b4.z; acc[2][3] += a4.z * b4.w;
            acc[3][0] += a4.w * b4.x; acc[3][1] += a4.w * b4.y; acc[3][2] += a4.w * b4.z; acc[3][3] += a4.w * b4.w;
        }
        __syncthreads();
    }
    #pragma unroll
    for (int i = 0; i < 4; i++) {
        int m = m0 + ty * 4 + i;
        #pragma unroll
        for (int j = 0; j < 4; j++) {
            int n = n0 + tx * 4 + j;
            if (n < N) {
                float v = acc[i][j] + (bias ? bias[n] : 0.f);
                if (PERM) {
                    int b = m & (B_ - 1), t = m >> 6;
                    C[((size_t)b * T_ + t) * V_ + n] = v;
                } else {
                    C[(size_t)m * N + n] = v;
                }
            }
        }
    }
}

// ---------------- per-step: finish previous cell, attention, softmax, ctx, build x ------
__device__ __forceinline__ void cell_update(int t, int b, int tid,
                                            const float* __restrict__ b_ih,
                                            const float* __restrict__ b_hh,
                                            float* h_out) {
    int j = tid;
    float gi = b_ih[j]       + b_hh[j];
    float gf = b_ih[j + 256] + b_hh[j + 256];
    float gg = b_ih[j + 512] + b_hh[j + 512];
    float go = b_ih[j + 768] + b_hh[j + 768];
    #pragma unroll
    for (int s = 0; s < SPLITK_; s++) {
        const float* gp = g_gpart + ((size_t)s * B_ + b) * NG_;
        gi += gp[j]; gf += gp[j + 256]; gg += gp[j + 512]; go += gp[j + 768];
    }
    float c  = g_c[b * DEC_ + tid];
    float cn = sigm(gf) * c + sigm(gi) * tanhf(gg);
    float hn = sigm(go) * tanhf(cn);
    g_c[b * DEC_ + tid] = cn;
    g_hall[((size_t)(t - 1) * B_ + b) * DEC_ + tid] = hn;
    if (h_out) h_out[tid] = hn;
}

__global__ void k_step(int t, const float* __restrict__ enc, const float* __restrict__ Wfull,
                       const float* __restrict__ embedding, const int* __restrict__ caption,
                       const float* __restrict__ b_ih, const float* __restrict__ b_hh,
                       float* __restrict__ alphas_out) {
    int b = blockIdx.x, tid = threadIdx.x;
    __shared__ float h_sh[256], att2[256], wf[256], sc[256], red[256];

    if (t > 0) cell_update(t, b, tid, b_ih, b_hh, h_sh);
    else       h_sh[tid] = g_h0[b * DEC_ + tid];
    wf[tid] = Wfull[tid];
    __syncthreads();

    // att2[j] = h . W_dec_att[j,:]  (WdaT is k-major -> coalesced)
    float a2 = 0.f;
    #pragma unroll 8
    for (int k = 0; k < 256; k++) a2 += h_sh[k] * g_WdaT[k * 256 + tid];
    att2[tid] = a2;
    __syncthreads();

    // scores: warp per p
    int lane = tid & 31, wid = tid >> 5;
    for (int p = wid; p < P_; p += 8) {
        const float* row = g_att1 + ((size_t)(b * P_ + p)) * ATT_;
        float s = 0.f;
        #pragma unroll
        for (int a = lane; a < 256; a += 32) {
            float v = row[a] + att2[a];
            s += fmaxf(v, 0.f) * wf[a];
        }
        #pragma unroll
        for (int o = 16; o > 0; o >>= 1) s += __shfl_down_sync(0xffffffffu, s, o);
        if (lane == 0) sc[p] = s;
    }
    __syncthreads();

    // softmax over P=196
    red[tid] = (tid < P_) ? sc[tid] : -1e30f;
    __syncthreads();
    for (int s = 128; s > 0; s >>= 1) { if (tid < s) red[tid] = fmaxf(red[tid], red[tid + s]); __syncthreads(); }
    float mx = red[0];
    __syncthreads();
    float ex = (tid < P_) ? expf(sc[tid] - mx) : 0.f;
    red[tid] = ex;
    __syncthreads();
    for (int s = 128; s > 0; s >>= 1) { if (tid < s) red[tid] += red[tid + s]; __syncthreads(); }
    float inv = 1.0f / red[0];
    __syncthreads();
    float alpha = ex * inv;
    if (tid < P_) {
        sc[tid] = alpha;
        alphas_out[((size_t)b * T_ + t) * P_ + tid] = alpha;
    }
    __syncthreads();

    // ctx[e] = sum_p alpha[p] * enc[b,p,e]  (coalesced over e)
    #pragma unroll
    for (int e0 = 0; e0 < 2; e0++) {
        int e = tid + e0 * 256;
        float s = 0.f;
        for (int p = 0; p < P_; p++) s += sc[p] * enc[((size_t)(b * P_ + p)) * ENC_ + e];
        g_x[b * KX_ + e] = s;
    }
    // x = [ctx | emb_t | h]
    int tok = caption[b * T_ + t];
    g_x[b * KX_ + ENC_ + tid]        = embedding[(size_t)tok * EMB_ + tid];
    g_x[b * KX_ + ENC_ + EMB_ + tid] = h_sh[tid];
}

__global__ void k_cell_final(const float* __restrict__ b_ih, const float* __restrict__ b_hh) {
    cell_update(T_, blockIdx.x, threadIdx.x, b_ih, b_hh, nullptr);
}

// ---------------- gates GEMM, split-K: gpart[sk][b][j] = sum_{k in chunk} x[b][k]*Wcat[j][k]
__global__ void k_gates() {
    __shared__ float Xs[64][68];
    __shared__ float Ws[64][68];
    int tid = threadIdx.x;
    int j0 = blockIdx.x * 64;
    int k0 = blockIdx.y * 64;
    #pragma unroll
    for (int r = 0; r < 16; r++) {
        int row = r * 4 + (tid >> 6);
        int k = tid & 63;
        Xs[k][row] = g_x[(size_t)row * KX_ + k0 + k];
        Ws[k][row] = g_Wcat[(size_t)(j0 + row) * KX_ + k0 + k];
    }
    __syncthreads();
    int tx = tid & 15, ty = tid >> 4;
    float acc[4][4] = {};
    #pragma unroll
    for (int kk = 0; kk < 64; kk++) {
        float4 xb = *(const float4*)&Xs[kk][ty * 4];
        float4 wj = *(const float4*)&Ws[kk][tx * 4];
        acc[0][0] += xb.x * wj.x; acc[0][1] += xb.x * wj.y; acc[0][2] += xb.x * wj.z; acc[0][3] += xb.x * wj.w;
        acc[1][0] += xb.y * wj.x; acc[1][1] += xb.y * wj.y; acc[1][2] += xb.y * wj.z; acc[1][3] += xb.y * wj.w;
        acc[2][0] += xb.z * wj.x; acc[2][1] += xb.z * wj.y; acc[2][2] += xb.z * wj.z; acc[2][3] += xb.z * wj.w;
        acc[3][0] += xb.w * wj.x; acc[3][1] += xb.w * wj.y; acc[3][2] += xb.w * wj.z; acc[3][3] += xb.w * wj.w;
    }
    #pragma unroll
    for (int bi = 0; bi < 4; bi++) {
        int b = ty * 4 + bi;
        #pragma unroll
        for (int ji = 0; ji < 4; ji++) {
            g_gpart[((size_t)blockIdx.y * B_ + b) * NG_ + j0 + tx * 4 + ji] = acc[bi][ji];
        }
    }
}

// ---------------- launch ----------------
extern "C" void kernel_launch(void* const* d_in, const int* in_sizes, int n_in,
                              void* d_out, int out_size) {
    const float* enc       = (const float*)d_in[0];
    const int*   caption   = (const int*)  d_in[1];
    const float* W_enc_att = (const float*)d_in[2];
    const float* W_dec_att = (const float*)d_in[3];
    const float* W_full    = (const float*)d_in[4];
    const float* embedding = (const float*)d_in[5];
    const float* W_init_h  = (const float*)d_in[6];
    const float* b_init_h  = (const float*)d_in[7];
    const float* W_init_c  = (const float*)d_in[8];
    const float* b_init_c  = (const float*)d_in[9];
    const float* W_ih      = (const float*)d_in[10];
    const float* b_ih      = (const float*)d_in[11];
    const float* W_hh      = (const float*)d_in[12];
    const float* b_hh      = (const float*)d_in[13];
    const float* W_out     = (const float*)d_in[14];
    const float* b_out     = (const float*)d_in[15];

    float* out    = (float*)d_out;
    float* preds  = out;                              // [B, T, V]
    float* alphas = out + (size_t)B_ * T_ * V_;       // [B, T, P]

    float *att1p, *hallp;
    cudaGetSymbolAddress((void**)&att1p, g_att1);
    cudaGetSymbolAddress((void**)&hallp, g_hall);

    // one-time prep
    k_prep<<<(NG_ * KX_ + ATT_ * DEC_ + 255) / 256, 256>>>(W_ih, W_hh, W_dec_att);
    k_init<<<B_, 256>>>(enc, W_init_h, b_init_h, W_init_c, b_init_c);
    // att1[b,p,a] = enc[b,p,:] . W_enc_att[a,:]   (M=12544, N=256, K=512)
    sgemm64<0><<<dim3(196, 4), 256>>>(enc, W_enc_att, nullptr, att1p, B_ * P_, ATT_, ENC_);

    // recurrence: 2 kernels per step
    for (int t = 0; t < T_; t++) {
        k_step<<<B_, 256>>>(t, enc, W_full, embedding, caption, b_ih, b_hh, alphas);
        k_gates<<<dim3(NG_ / 64, SPLITK_), 256>>>();
    }
    k_cell_final<<<B_, 256>>>(b_ih, b_hh);

    // batched logits: [T*B, DEC] @ W_out^T, permuted store into [B, T, V]
    sgemm64<1><<<dim3((T_ * B_) / 64, (V_ + 63) / 64), 256>>>(hallp, W_out, b_out, preds,
                                                              T_ * B_, V_, DEC_);
}

// round 3
// speedup vs baseline: 1.6520x; 1.6426x over previous
#include <cuda_runtime.h>
#include <math.h>

#define B_    64
#define P_    196
#define ENC_  512
#define EMB_  256
#define ATT_  256
#define DEC_  256
#define V_    10000
#define T_    44
#define NG_   1024           // 4*DEC
#define KX2_  768            // ENC + DEC (emb part hoisted out of loop)
#define SPLITK_ 12           // gates GEMM K chunks of 64

// ---------------- device scratch (static: no allocation allowed) ----------------
__device__ float g_att1[B_ * P_ * ATT_];        // encoder attention keys
__device__ float g_WdaT[ATT_ * DEC_];           // W_dec_att transposed [k][j]
__device__ float g_Wcat2[NG_ * KX2_];           // [W_ih[:, :512] | W_hh] row-major [j][k]
__device__ float g_Wemb[NG_ * EMB_];            // W_ih[:, 512:768]
__device__ float g_embx[T_ * B_ * EMB_];        // gathered embeddings, all steps
__device__ float g_gemb[T_ * B_ * NG_];         // precomputed emb gate contributions
__device__ float g_h0[B_ * DEC_];
__device__ float g_c[B_ * DEC_];
__device__ float g_x[B_ * KX2_];                // per-step LSTM input [ctx | h]
__device__ float g_att2[B_ * ATT_];
__device__ float g_scores[B_ * P_];
__device__ float g_gpart[SPLITK_ * B_ * NG_];   // split-K gate partials
__device__ float g_hall[T_ * B_ * DEC_];        // all hidden states for batched logits

__device__ __forceinline__ float sigm(float x) { return 1.0f / (1.0f + expf(-x)); }

// ---------------- one-time weight prep (transpose / concat / gather) ----------------
__global__ void k_prep(const float* __restrict__ W_ih, const float* __restrict__ W_hh,
                       const float* __restrict__ W_dec_att,
                       const float* __restrict__ embedding, const int* __restrict__ caption) {
    int idx = blockIdx.x * blockDim.x + threadIdx.x;
    if (idx < NG_ * KX2_) {
        int j = idx / KX2_, k = idx % KX2_;
        g_Wcat2[idx] = (k < 512) ? W_ih[j * 768 + k] : W_hh[j * 256 + (k - 512)];
    }
    int i2 = idx - NG_ * KX2_;
    if (i2 >= 0 && i2 < ATT_ * DEC_) {
        int k = i2 >> 8, j = i2 & 255;
        g_WdaT[i2] = W_dec_att[j * 256 + k];
    }
    int i3 = i2 - ATT_ * DEC_;
    if (i3 >= 0 && i3 < NG_ * EMB_) {
        int j = i3 >> 8, k = i3 & 255;
        g_Wemb[i3] = W_ih[j * 768 + 512 + k];
    }
    int i4 = i3 - NG_ * EMB_;
    if (i4 >= 0 && i4 < T_ * B_ * EMB_) {
        int m = i4 >> 8, k = i4 & 255;
        int b = m & (B_ - 1), t = m >> 6;
        g_embx[i4] = embedding[(size_t)caption[b * T_ + t] * EMB_ + k];
    }
}

// ---------------- init h0/c0 from mean-pooled encoder ----------------
__global__ void k_init(const float* __restrict__ enc,
                       const float* __restrict__ W_init_h, const float* __restrict__ b_init_h,
                       const float* __restrict__ W_init_c, const float* __restrict__ b_init_c) {
    int b = blockIdx.x, tid = threadIdx.x;
    __shared__ float avg[ENC_];
    #pragma unroll
    for (int e0 = 0; e0 < 2; e0++) {
        int e = tid + e0 * 256;
        float s = 0.f;
        for (int p = 0; p < P_; p++) s += enc[((size_t)(b * P_ + p)) * ENC_ + e];
        avg[e] = s * (1.0f / (float)P_);
    }
    __syncthreads();
    float h = b_init_h[tid], c = b_init_c[tid];
    const float* wh = W_init_h + (size_t)tid * ENC_;
    const float* wc = W_init_c + (size_t)tid * ENC_;
    #pragma unroll 8
    for (int k = 0; k < ENC_; k++) { h += avg[k] * wh[k]; c += avg[k] * wc[k]; }
    g_h0[b * DEC_ + tid] = h;
    g_c[b * DEC_ + tid] = c;
}

// ---------------- 128x128 tiled SGEMM, 8x8 per thread: C[m][n] = A[m][k]*Bm[n][k] (+bias)
// PERM=1: row m encodes (t*B + b); store to C[(b*T + t)*V + n] (logits epilogue)
// Requires M % 128 == 0, K % 16 == 0. N guarded.
template<int PERM>
__global__ __launch_bounds__(256) void sgemm128(
        const float* __restrict__ A, const float* __restrict__ Bm,
        const float* __restrict__ bias, float* __restrict__ C,
        int M, int N, int K) {
    __shared__ float As[16][132];
    __shared__ float Bs[16][132];
    int tid = threadIdx.x;
    int m0 = blockIdx.x * 128, n0 = blockIdx.y * 128;
    int tx = tid & 15, ty = tid >> 4;
    int lrow = tid >> 2;           // 0..63
    int lkc  = (tid & 3) * 4;      // 0,4,8,12
    float acc[8][8] = {};
    for (int k0 = 0; k0 < K; k0 += 16) {
        #pragma unroll
        for (int i = 0; i < 2; i++) {
            int row = lrow + i * 64;
            float4 av = *(const float4*)&A[(size_t)(m0 + row) * K + k0 + lkc];
            As[lkc + 0][row] = av.x; As[lkc + 1][row] = av.y;
            As[lkc + 2][row] = av.z; As[lkc + 3][row] = av.w;
            float4 bv = make_float4(0.f, 0.f, 0.f, 0.f);
            if (n0 + row < N) bv = *(const float4*)&Bm[(size_t)(n0 + row) * K + k0 + lkc];
            Bs[lkc + 0][row] = bv.x; Bs[lkc + 1][row] = bv.y;
            Bs[lkc + 2][row] = bv.z; Bs[lkc + 3][row] = bv.w;
        }
        __syncthreads();
        #pragma unroll
        for (int kk = 0; kk < 16; kk++) {
            float a[8], b[8];
            *(float4*)&a[0] = *(const float4*)&As[kk][ty * 4];
            *(float4*)&a[4] = *(const float4*)&As[kk][64 + ty * 4];
            *(float4*)&b[0] = *(const float4*)&Bs[kk][tx * 4];
            *(float4*)&b[4] = *(const float4*)&Bs[kk][64 + tx * 4];
            #pragma unroll
            for (int i = 0; i < 8; i++)
                #pragma unroll
                for (int j = 0; j < 8; j++) acc[i][j] += a[i] * b[j];
        }
        __syncthreads();
    }
    #pragma unroll
    for (int i = 0; i < 8; i++) {
        int m = m0 + (i < 4 ? ty * 4 + i : 64 + ty * 4 + (i - 4));
        #pragma unroll
        for (int j = 0; j < 8; j++) {
            int n = n0 + (j < 4 ? tx * 4 + j : 64 + tx * 4 + (j - 4));
            if (n < N) {
                float v = acc[i][j] + (bias ? bias[n] : 0.f);
                if (PERM) {
                    int b = m & (B_ - 1), t = m >> 6;
                    C[((size_t)b * T_ + t) * V_ + n] = v;
                } else {
                    C[(size_t)m * N + n] = v;
                }
            }
        }
    }
}

// ---------------- cell update (finish previous step's gates) + att2 projection --------
__global__ void k_cell_att2(int t, const float* __restrict__ b_ih,
                            const float* __restrict__ b_hh) {
    int b = blockIdx.x, tid = threadIdx.x;
    __shared__ float h_sh[256];
    if (t > 0) {
        const float* ge = g_gemb + ((size_t)(t - 1) * B_ + b) * NG_;
        float gi = b_ih[tid]       + b_hh[tid]       + ge[tid];
        float gf = b_ih[tid + 256] + b_hh[tid + 256] + ge[tid + 256];
        float gg = b_ih[tid + 512] + b_hh[tid + 512] + ge[tid + 512];
        float go = b_ih[tid + 768] + b_hh[tid + 768] + ge[tid + 768];
        #pragma unroll
        for (int s = 0; s < SPLITK_; s++) {
            const float* gp = g_gpart + ((size_t)s * B_ + b) * NG_;
            gi += gp[tid]; gf += gp[tid + 256]; gg += gp[tid + 512]; go += gp[tid + 768];
        }
        float c  = g_c[b * DEC_ + tid];
        float cn = sigm(gf) * c + sigm(gi) * tanhf(gg);
        float hn = sigm(go) * tanhf(cn);
        g_c[b * DEC_ + tid] = cn;
        g_hall[((size_t)(t - 1) * B_ + b) * DEC_ + tid] = hn;
        h_sh[tid] = hn;
    } else {
        h_sh[tid] = g_h0[b * DEC_ + tid];
    }
    if (t == T_) return;   // final call: only finish last cell
    g_x[b * KX2_ + ENC_ + tid] = h_sh[tid];
    __syncthreads();
    float a2 = 0.f;
    #pragma unroll 8
    for (int k = 0; k < 256; k++) a2 += h_sh[k] * g_WdaT[k * 256 + tid];
    g_att2[b * 256 + tid] = a2;
}

// ---------------- scores: grid (B, 7); each block handles 28 p's -----------------------
__global__ void k_scores(const float* __restrict__ Wfull) {
    int b = blockIdx.x, tid = threadIdx.x;
    int p0 = blockIdx.y * 28;
    __shared__ float att2s[256], wfs[256];
    att2s[tid] = g_att2[b * 256 + tid];
    wfs[tid]   = Wfull[tid];
    __syncthreads();
    int lane = tid & 31, wid = tid >> 5;
    for (int p = p0 + wid; p < p0 + 28; p += 8) {
        const float* row = g_att1 + ((size_t)(b * P_ + p)) * ATT_;
        float s = 0.f;
        #pragma unroll
        for (int a = lane; a < 256; a += 32) {
            float v = row[a] + att2s[a];
            s += fmaxf(v, 0.f) * wfs[a];
        }
        #pragma unroll
        for (int o = 16; o > 0; o >>= 1) s += __shfl_down_sync(0xffffffffu, s, o);
        if (lane == 0) g_scores[b * P_ + p] = s;
    }
}

// ---------------- softmax (recomputed per block) + ctx for one 64-e chunk --------------
__global__ void k_softmax_ctx(int t, const float* __restrict__ enc,
                              float* __restrict__ alphas_out) {
    int b = blockIdx.x, tid = threadIdx.x;
    int e0 = blockIdx.y * 64;
    __shared__ float sc[256], red[256];
    float sv = (tid < P_) ? g_scores[b * P_ + tid] : -1e30f;
    red[tid] = sv;
    __syncthreads();
    for (int s = 128; s > 0; s >>= 1) { if (tid < s) red[tid] = fmaxf(red[tid], red[tid + s]); __syncthreads(); }
    float mx = red[0];
    __syncthreads();
    float ex = (tid < P_) ? expf(sv - mx) : 0.f;
    red[tid] = ex;
    __syncthreads();
    for (int s = 128; s > 0; s >>= 1) { if (tid < s) red[tid] += red[tid + s]; __syncthreads(); }
    float inv = 1.0f / red[0];
    float alpha = ex * inv;
    sc[tid] = alpha;
    if (blockIdx.y == 0 && tid < P_)
        alphas_out[((size_t)b * T_ + t) * P_ + tid] = alpha;
    __syncthreads();
    // ctx: 64 e's, 4 threads per e
    int e = tid & 63, ps = tid >> 6;
    float s = 0.f;
    for (int p = ps; p < P_; p += 4)
        s += sc[p] * enc[((size_t)(b * P_ + p)) * ENC_ + e0 + e];
    red[tid] = s;
    __syncthreads();
    if (tid < 64)
        g_x[b * KX2_ + e0 + tid] = red[tid] + red[tid + 64] + red[tid + 128] + red[tid + 192];
}

// ---------------- gates GEMM, split-K over K=768: gpart[sk][b][j] ----------------------
__global__ void k_gates() {
    __shared__ float Xs[64][68];
    __shared__ float Ws[64][68];
    int tid = threadIdx.x;
    int j0 = blockIdx.x * 64;
    int k0 = blockIdx.y * 64;
    #pragma unroll
    for (int r = 0; r < 16; r++) {
        int row = r * 4 + (tid >> 6);
        int k = tid & 63;
        Xs[k][row] = g_x[(size_t)row * KX2_ + k0 + k];
        Ws[k][row] = g_Wcat2[(size_t)(j0 + row) * KX2_ + k0 + k];
    }
    __syncthreads();
    int tx = tid & 15, ty = tid >> 4;
    float acc[4][4] = {};
    #pragma unroll
    for (int kk = 0; kk < 64; kk++) {
        float4 xb = *(const float4*)&Xs[kk][ty * 4];
        float4 wj = *(const float4*)&Ws[kk][tx * 4];
        acc[0][0] += xb.x * wj.x; acc[0][1] += xb.x * wj.y; acc[0][2] += xb.x * wj.z; acc[0][3] += xb.x * wj.w;
        acc[1][0] += xb.y * wj.x; acc[1][1] += xb.y * wj.y; acc[1][2] += xb.y * wj.z; acc[1][3] += xb.y * wj.w;
        acc[2][0] += xb.z * wj.x; acc[2][1] += xb.z * wj.y; acc[2][2] += xb.z * wj.z; acc[2][3] += xb.z * wj.w;
        acc[3][0] += xb.w * wj.x; acc[3][1] += xb.w * wj.y; acc[3][2] += xb.w * wj.z; acc[3][3] += xb.w * wj.w;
    }
    #pragma unroll
    for (int bi = 0; bi < 4; bi++) {
        int b = ty * 4 + bi;
        #pragma unroll
        for (int ji = 0; ji < 4; ji++) {
            g_gpart[((size_t)blockIdx.y * B_ + b) * NG_ + j0 + tx * 4 + ji] = acc[bi][ji];
        }
    }
}

// ---------------- launch ----------------
extern "C" void kernel_launch(void* const* d_in, const int* in_sizes, int n_in,
                              void* d_out, int out_size) {
    const float* enc       = (const float*)d_in[0];
    const int*   caption   = (const int*)  d_in[1];
    const float* W_enc_att = (const float*)d_in[2];
    const float* W_dec_att = (const float*)d_in[3];
    const float* W_full    = (const float*)d_in[4];
    const float* embedding = (const float*)d_in[5];
    const float* W_init_h  = (const float*)d_in[6];
    const float* b_init_h  = (const float*)d_in[7];
    const float* W_init_c  = (const float*)d_in[8];
    const float* b_init_c  = (const float*)d_in[9];
    const float* W_ih      = (const float*)d_in[10];
    const float* b_ih      = (const float*)d_in[11];
    const float* W_hh      = (const float*)d_in[12];
    const float* b_hh      = (const float*)d_in[13];
    const float* W_out     = (const float*)d_in[14];
    const float* b_out     = (const float*)d_in[15];

    float* out    = (float*)d_out;
    float* preds  = out;                              // [B, T, V]
    float* alphas = out + (size_t)B_ * T_ * V_;       // [B, T, P]

    float *att1p, *hallp, *embxp, *wembp, *gembp;
    cudaGetSymbolAddress((void**)&att1p, g_att1);
    cudaGetSymbolAddress((void**)&hallp, g_hall);
    cudaGetSymbolAddress((void**)&embxp, g_embx);
    cudaGetSymbolAddress((void**)&wembp, g_Wemb);
    cudaGetSymbolAddress((void**)&gembp, g_gemb);

    // one-time prep
    int prep_total = NG_ * KX2_ + ATT_ * DEC_ + NG_ * EMB_ + T_ * B_ * EMB_;
    k_prep<<<(prep_total + 255) / 256, 256>>>(W_ih, W_hh, W_dec_att, embedding, caption);
    k_init<<<B_, 256>>>(enc, W_init_h, b_init_h, W_init_c, b_init_c);
    // att1[b,p,a] = enc[b,p,:] . W_enc_att[a,:]   (M=12544, N=256, K=512)
    sgemm128<0><<<dim3(98, 2), 256>>>(enc, W_enc_att, nullptr, att1p, B_ * P_, ATT_, ENC_);
    // gemb[t*B+b][j] = embx . Wemb^T               (M=2816, N=1024, K=256)
    sgemm128<0><<<dim3(22, 8), 256>>>(embxp, wembp, nullptr, gembp, T_ * B_, NG_, EMB_);

    // recurrence: 4 wide kernels per step
    for (int t = 0; t < T_; t++) {
        k_cell_att2<<<B_, 256>>>(t, b_ih, b_hh);
        k_scores<<<dim3(B_, 7), 256>>>(W_full);
        k_softmax_ctx<<<dim3(B_, 8), 256>>>(t, enc, alphas);
        k_gates<<<dim3(NG_ / 64, SPLITK_), 256>>>();
    }
    k_cell_att2<<<B_, 256>>>(T_, b_ih, b_hh);

    // batched logits: [T*B, DEC] @ W_out^T, permuted store into [B, T, V]
    sgemm128<1><<<dim3((T_ * B_) / 128, (V_ + 127) / 128), 256>>>(hallp, W_out, b_out, preds,
                                                                  T_ * B_, V_, DEC_);
}